// round 15
// baseline (speedup 1.0000x reference)
#include <cuda_runtime.h>
#include <cuda_bf16.h>
#include <math.h>

#define BB 2
#define CC 256
#define H2 128
#define W2 128
#define NWIN 512
#define NPOS 64
#define NHEADS 8
#define HD 32
#define ATT_SCALE 0.17677669529663687f
#define APAD 68     // probs row stride in smem (strided-n AV reads conflict-free)
#define LHP 72      // lh/q row stride: 72 ≡ 8 (mod 32) -> conv conflict-free

typedef unsigned long long ull;
typedef unsigned int u32;

__device__ __forceinline__ ull pack2(float lo, float hi) {
    ull r; asm("mov.b64 %0, {%1,%2};" : "=l"(r) : "f"(lo), "f"(hi)); return r;
}
__device__ __forceinline__ void fma2(ull& d, ull a, ull b) {
    asm("fma.rn.f32x2 %0, %1, %2, %0;" : "+l"(d) : "l"(a), "l"(b));
}
__device__ __forceinline__ float2 unpack2(ull v) {
    float2 f; asm("mov.b64 {%0,%1}, %2;" : "=f"(f.x), "=f"(f.y) : "l"(v)); return f;
}
__device__ __forceinline__ void cpa16(u32 dst, const void* src) {
    asm volatile("cp.async.cg.shared.global [%0], [%1], 16;" :: "r"(dst), "l"(src));
}
#define CP_COMMIT() asm volatile("cp.async.commit_group;")
#define CP_WAIT(n)  asm volatile("cp.async.wait_group %0;" :: "n"(n))

// Scratch in window layout: [win][ch][p]
__device__ float g_llw  [NWIN * CC * NPOS];
__device__ float g_lhw  [NWIN * CC * NPOS];
__device__ float g_hlw  [NWIN * CC * NPOS];
__device__ float g_hhw  [NWIN * CC * NPOS];
__device__ float g_relu [NWIN * CC * NPOS];
__device__ float g_llout[NWIN * CC * NPOS];
// softmaxed attention probabilities: [win*8+h][n][m]
__device__ float g_attn [NWIN * NHEADS * NPOS * NPOS];

// ---------------------------------------------------------------------------
// Kernel A: forward wavelet, 2 pixels per thread
// ---------------------------------------------------------------------------
__global__ void wt_kernel(const float* __restrict__ x, const float* __restrict__ wf) {
    int idx = blockIdx.x * blockDim.x + threadIdx.x;
    int xp = idx & 63;
    int y  = (idx >> 6) & 127;
    int ch = (idx >> 13) & 255;
    int b  = idx >> 21;
    int xx = xp << 1;

    const float* px = x + (((size_t)(b * CC + ch) * 256 + 2 * y) * 256 + 2 * xx);
    float4 r0 = *(const float4*)px;
    float4 r1 = *(const float4*)(px + 256);

    int win = b * 256 + (y >> 3) * 16 + (xx >> 3);
    int off = (win * CC + ch) * NPOS + (y & 7) * 8 + (xx & 7);
    const float* w = wf + ch * 16;

    float2 ll, lh, hl, hh;
    ll.x = w[0]*r0.x + w[1]*r0.y + w[2]*r1.x + w[3]*r1.y;
    ll.y = w[0]*r0.z + w[1]*r0.w + w[2]*r1.z + w[3]*r1.w;
    lh.x = w[4]*r0.x + w[5]*r0.y + w[6]*r1.x + w[7]*r1.y;
    lh.y = w[4]*r0.z + w[5]*r0.w + w[6]*r1.z + w[7]*r1.w;
    hl.x = w[8]*r0.x + w[9]*r0.y + w[10]*r1.x + w[11]*r1.y;
    hl.y = w[8]*r0.z + w[9]*r0.w + w[10]*r1.z + w[11]*r1.w;
    hh.x = w[12]*r0.x + w[13]*r0.y + w[14]*r1.x + w[15]*r1.y;
    hh.y = w[12]*r0.z + w[13]*r0.w + w[14]*r1.z + w[15]*r1.w;

    *(float2*)&g_llw[off] = ll;
    *(float2*)&g_lhw[off] = lh;
    *(float2*)&g_hlw[off] = hl;
    *(float2*)&g_hhw[off] = hh;
}

// ---------------------------------------------------------------------------
// Kernel B1: per-(window, head) conv + QK + softmax -> g_attn. Fully parallel.
// ---------------------------------------------------------------------------
__global__ void __launch_bounds__(256) qk_kernel(const float* __restrict__ dw_w,
                                                 const float* __restrict__ dw_b,
                                                 const float* __restrict__ ab) {
    extern __shared__ float sm[];
    float* s_w   = sm;          // 800
    float* s_lh  = sm + 800;    // 2296
    float* s_k   = sm + 3096;   // 2048
    float* s_q   = sm + 5144;   // 2296
    float* s_abr = sm + 7440;   // 64

    const int bid = blockIdx.x;
    const int win = bid >> 3, h = bid & 7;
    const int tid = threadIdx.x;
    const size_t hs = ((size_t)win * CC + h * HD) * NPOS;

    const u32 u_lh = (u32)__cvta_generic_to_shared(s_lh);
    const u32 u_w  = (u32)__cvta_generic_to_shared(s_w);
    const u32 u_k  = (u32)__cvta_generic_to_shared(s_k);

    {   // Group1: lh (padded rows) + conv weights
        const float4* src = (const float4*)(g_lhw + hs);
        #pragma unroll
        for (int kk = 0; kk < 2; ++kk) {
            int i = tid + kk * 256;
            int d = i >> 4, c = i & 15;
            cpa16(u_lh + (u32)(d * 18 + c) * 16, src + i);
        }
        if (tid < 200) cpa16(u_w + tid * 16, (const float4*)(dw_w + h * HD * 25) + tid);
        CP_COMMIT();
    }
    {   // Group2: k
        const float4* src = (const float4*)(g_hlw + hs);
        cpa16(u_k + tid * 16, src + tid);
        cpa16(u_k + (tid + 256) * 16, src + tid + 256);
        CP_COMMIT();
    }
    if (tid < 64) s_abr[tid] = ab[h * 64 + tid];

    const int cd  = tid >> 3;
    const int cix = tid & 7;
    const int tn  = (tid >> 4) << 2;
    const int tm  = (tid & 15) << 2;

    CP_WAIT(1);
    __syncthreads();

    // conv: q = dw5x5(lh) + bias
    {
        float wv[25];
        #pragma unroll
        for (int t = 0; t < 25; ++t) wv[t] = s_w[cd * 25 + t];
        float bias = __ldg(&dw_b[h * HD + cd]);
        #pragma unroll
        for (int iy = 0; iy < 8; ++iy) {
            float acc = bias;
            #pragma unroll
            for (int ky = 0; ky < 5; ++ky) {
                int yy = iy + ky - 2;
                if (yy < 0 || yy > 7) continue;
                #pragma unroll
                for (int kx = 0; kx < 5; ++kx) {
                    int xc = cix + kx - 2;
                    if (xc >= 0 && xc < 8)
                        acc += wv[ky * 5 + kx] * s_lh[cd * LHP + yy * 8 + xc];
                }
            }
            s_q[cd * LHP + iy * 8 + cix] = acc;
        }
    }
    CP_WAIT(0);
    __syncthreads();

    // QK + in-register softmax -> g_attn
    {
        ull a0[4] = {}, a1[4] = {};
        #pragma unroll 8
        for (int d = 0; d < HD; ++d) {
            ulonglong2 k2 = *(const ulonglong2*)&s_k[d * 64 + tm];
            float4 q4 = *(const float4*)&s_q[d * LHP + tn];
            ull qp[4] = {pack2(q4.x, q4.x), pack2(q4.y, q4.y),
                         pack2(q4.z, q4.z), pack2(q4.w, q4.w)};
            #pragma unroll
            for (int i = 0; i < 4; ++i) { fma2(a0[i], qp[i], k2.x); fma2(a1[i], qp[i], k2.y); }
        }
        float* pout = g_attn + (size_t)bid * (NPOS * NPOS);
        #pragma unroll
        for (int i = 0; i < 4; ++i) {
            int n = tn + i, yn = n >> 3, xn = n & 7;
            float2 pa = unpack2(a0[i]);
            float2 pb = unpack2(a1[i]);
            float raw[4] = {pa.x, pa.y, pb.x, pb.y};
            float vals[4];
            #pragma unroll
            for (int j = 0; j < 4; ++j) {
                int m = tm + j, ym = m >> 3, xm = m & 7;
                vals[j] = raw[j] * ATT_SCALE + s_abr[abs(yn - ym) * 8 + abs(xn - xm)];
            }
            float mx = fmaxf(fmaxf(vals[0], vals[1]), fmaxf(vals[2], vals[3]));
            mx = fmaxf(mx, __shfl_xor_sync(0xffffffff, mx, 1));
            mx = fmaxf(mx, __shfl_xor_sync(0xffffffff, mx, 2));
            mx = fmaxf(mx, __shfl_xor_sync(0xffffffff, mx, 4));
            mx = fmaxf(mx, __shfl_xor_sync(0xffffffff, mx, 8));
            float e0 = __expf(vals[0] - mx), e1 = __expf(vals[1] - mx);
            float e2 = __expf(vals[2] - mx), e3 = __expf(vals[3] - mx);
            float sum = e0 + e1 + e2 + e3;
            sum += __shfl_xor_sync(0xffffffff, sum, 1);
            sum += __shfl_xor_sync(0xffffffff, sum, 2);
            sum += __shfl_xor_sync(0xffffffff, sum, 4);
            sum += __shfl_xor_sync(0xffffffff, sum, 8);
            float inv = 1.0f / sum;
            *(float4*)&pout[n * 64 + tm] = make_float4(e0 * inv, e1 * inv, e2 * inv, e3 * inv);
        }
    }
}

// ---------------------------------------------------------------------------
// Kernel B2: serial AV cascade per window; probs double-buffered via cp.async
// ---------------------------------------------------------------------------
__global__ void __launch_bounds__(256) av_kernel() {
    extern __shared__ float sm[];
    float* s_v  = sm;          // 2048
    float* bufs = sm + 2048;   // 2 x 4352

    const int win = blockIdx.x;
    const int tid = threadIdx.x;
    const size_t wbase = (size_t)win * CC * NPOS;
    const u32 u_buf = (u32)__cvta_generic_to_shared(bufs);

    const int ad0 = (tid >> 4) << 1;   // 2 d's per thread
    const int ln  = tid & 15;          // n = ln + 16j

    {   // v(head0)
        const float4* sv = (const float4*)(g_llw + wbase);
        float4* dv = (float4*)s_v;
        dv[tid] = sv[tid]; dv[tid + 256] = sv[tid + 256];
    }
    // prefetch probs for heads 0 and 1
    #pragma unroll
    for (int g = 0; g < 2; ++g) {
        const float4* src = (const float4*)(g_attn + (size_t)(win * NHEADS + g) * (NPOS * NPOS));
        u32 dst = u_buf + (u32)(g * 4352 * 4);
        #pragma unroll
        for (int kk = 0; kk < 4; ++kk) {
            int c = tid + kk * 256;
            int row = c >> 4, col = c & 15;
            cpa16(dst + (u32)(row * APAD + col * 4) * 4, src + c);
        }
        CP_COMMIT();
    }

    float vnew[2][4];
    for (int h = 0; h < NHEADS; ++h) {
        if (h == NHEADS - 1) { CP_WAIT(0); } else { CP_WAIT(1); }
        __syncthreads();               // AV(h-1) done everywhere + probs(h) visible

        if (h > 0) {                   // deferred v-update
            #pragma unroll
            for (int i = 0; i < 2; ++i)
                #pragma unroll
                for (int j = 0; j < 4; ++j)
                    s_v[(ad0 + i) * 64 + ln + 16 * j] = vnew[i][j];
        }
        __syncwarp();

        const float* s_attn = bufs + (h & 1) * 4352;

        float pll[2][4];
        if (h < NHEADS - 1) {
            const float* src = g_llw + wbase + (size_t)(h + 1) * HD * NPOS;
            #pragma unroll
            for (int i = 0; i < 2; ++i)
                #pragma unroll
                for (int j = 0; j < 4; ++j)
                    pll[i][j] = __ldg(&src[(ad0 + i) * 64 + ln + 16 * j]);
        }

        ull acc2[2][4];
        #pragma unroll
        for (int i = 0; i < 2; ++i)
            #pragma unroll
            for (int j = 0; j < 4; ++j) acc2[i][j] = 0ULL;
        #pragma unroll 4
        for (int mq = 0; mq < 16; ++mq) {
            ulonglong2 vv0 = *(const ulonglong2*)&s_v[ad0 * 64 + mq * 4];
            ulonglong2 vv1 = *(const ulonglong2*)&s_v[(ad0 + 1) * 64 + mq * 4];
            ulonglong2 aa[4];
            #pragma unroll
            for (int j = 0; j < 4; ++j)
                aa[j] = *(const ulonglong2*)&s_attn[(ln + 16 * j) * APAD + mq * 4];
            #pragma unroll
            for (int j = 0; j < 4; ++j) {
                fma2(acc2[0][j], vv0.x, aa[j].x); fma2(acc2[0][j], vv0.y, aa[j].y);
                fma2(acc2[1][j], vv1.x, aa[j].x); fma2(acc2[1][j], vv1.y, aa[j].y);
            }
        }
        {
            size_t ob = wbase + (size_t)h * HD * NPOS;
            #pragma unroll
            for (int i = 0; i < 2; ++i) {
                int d = ad0 + i;
                #pragma unroll
                for (int j = 0; j < 4; ++j) {
                    float2 p = unpack2(acc2[i][j]);
                    float val = p.x + p.y;
                    g_relu[ob + d * 64 + ln + 16 * j] = fmaxf(val, 0.f);
                    if (h < NHEADS - 1) vnew[i][j] = val + pll[i][j];
                }
            }
        }
        __syncthreads();               // AV(h) fully done -> buf[h&1] reusable
        if (h + 2 < NHEADS) {          // prefetch probs(h+2) into buf[h&1]
            const float4* src = (const float4*)(g_attn + (size_t)(win * NHEADS + h + 2) * (NPOS * NPOS));
            u32 dst = u_buf + (u32)((h & 1) * 4352 * 4);
            #pragma unroll
            for (int kk = 0; kk < 4; ++kk) {
                int c = tid + kk * 256;
                int row = c >> 4, col = c & 15;
                cpa16(dst + (u32)(row * APAD + col * 4) * 4, src + c);
            }
            CP_COMMIT();
        }
    }
}

// ---------------------------------------------------------------------------
// Kernel B3: batched proj GEMM, 512 threads, 2 o-pairs x 8 n per thread
// (acc = 16 ull = 32 regs -> ~64 total -> 2 CTAs x 512 thr = 32 warps/SM)
// ---------------------------------------------------------------------------
__global__ void __launch_bounds__(512) proj_kernel(const float* __restrict__ pw,
                                                   const float* __restrict__ pb) {
    extern __shared__ float psm[];
    float* sW  = psm;                       // [cl][o], stride 258
    ull*   sXd = (ull*)(psm + 32 * 258);    // [cl][n] duplicated pairs

    int win = blockIdx.x;
    int tid = threadIdx.x;
    int to  = (tid >> 3) << 2;              // 4 o's = 2 o-pairs
    int lnn = tid & 7;                      // n = lnn + 8j

    ull acc2[2][8];
    #pragma unroll
    for (int i = 0; i < 2; ++i)
        #pragma unroll
        for (int j = 0; j < 8; ++j) acc2[i][j] = 0ULL;

    for (int c0 = 0; c0 < CC; c0 += 32) {
        #pragma unroll
        for (int k = 0; k < 16; ++k) {
            int i = tid + k * 512;
            int o = i >> 5, cl = i & 31;
            sW[cl * 258 + o] = pw[o * 256 + c0 + cl];
        }
        {
            const float* xs = g_relu + (size_t)(win * CC + c0) * NPOS;
            #pragma unroll
            for (int k = 0; k < 4; ++k) {
                int j = tid + k * 512;
                float v = xs[j];
                sXd[j] = pack2(v, v);
            }
        }
        __syncthreads();

        #pragma unroll 4
        for (int cl = 0; cl < 32; ++cl) {
            ull w2[2];
            w2[0] = *(const ull*)&sW[cl * 258 + to];
            w2[1] = *(const ull*)&sW[cl * 258 + to + 2];
            ull xd[8];
            #pragma unroll
            for (int j = 0; j < 8; ++j) xd[j] = sXd[cl * 64 + lnn + 8 * j];
            #pragma unroll
            for (int i = 0; i < 2; ++i)
                #pragma unroll
                for (int j = 0; j < 8; ++j) fma2(acc2[i][j], w2[i], xd[j]);
        }
        __syncthreads();
    }

    #pragma unroll
    for (int i = 0; i < 2; ++i) {
        int o0 = to + 2 * i;
        float b0 = pb[o0], b1 = pb[o0 + 1];
        float* out0 = g_llout + (size_t)(win * CC + o0) * NPOS;
        float* out1 = out0 + NPOS;
        #pragma unroll
        for (int j = 0; j < 8; ++j) {
            float2 p = unpack2(acc2[i][j]);
            int n = lnn + 8 * j;
            out0[n] = p.x + b0;
            out1[n] = p.y + b1;
        }
    }
}

// ---------------------------------------------------------------------------
// Kernel C: inverse wavelet, 2 cells per thread
// ---------------------------------------------------------------------------
__global__ void iwt_kernel(const float* __restrict__ iwf, float* __restrict__ out) {
    int idx = blockIdx.x * blockDim.x + threadIdx.x;
    int xp = idx & 63;
    int y  = (idx >> 6) & 127;
    int ch = (idx >> 13) & 255;
    int b  = idx >> 21;
    int xx = xp << 1;

    int win = b * 256 + (y >> 3) * 16 + (xx >> 3);
    int off = (win * CC + ch) * NPOS + (y & 7) * 8 + (xx & 7);
    float2 v0 = *(const float2*)&g_llout[off];
    float2 v1 = *(const float2*)&g_lhw[off];
    float2 v2 = *(const float2*)&g_hlw[off];
    float2 v3 = *(const float2*)&g_hhw[off];

    const float* w = iwf + ch * 16;
    float* po = out + (((size_t)(b * CC + ch) * 256 + 2 * y) * 256 + 2 * xx);

    float4 r0, r1;
    r0.x = w[0]*v0.x + w[4]*v1.x + w[8]*v2.x  + w[12]*v3.x;
    r0.y = w[1]*v0.x + w[5]*v1.x + w[9]*v2.x  + w[13]*v3.x;
    r0.z = w[0]*v0.y + w[4]*v1.y + w[8]*v2.y  + w[12]*v3.y;
    r0.w = w[1]*v0.y + w[5]*v1.y + w[9]*v2.y  + w[13]*v3.y;
    r1.x = w[2]*v0.x + w[6]*v1.x + w[10]*v2.x + w[14]*v3.x;
    r1.y = w[3]*v0.x + w[7]*v1.x + w[11]*v2.x + w[15]*v3.x;
    r1.z = w[2]*v0.y + w[6]*v1.y + w[10]*v2.y + w[14]*v3.y;
    r1.w = w[3]*v0.y + w[7]*v1.y + w[11]*v2.y + w[15]*v3.y;

    *(float4*)po         = r0;
    *(float4*)(po + 256) = r1;
}

// ---------------------------------------------------------------------------
extern "C" void kernel_launch(void* const* d_in, const int* in_sizes, int n_in,
                              void* d_out, int out_size) {
    const float* x    = (const float*)d_in[0];
    const float* wtf  = (const float*)d_in[1];
    const float* iwtf = (const float*)d_in[2];
    const float* dww  = (const float*)d_in[3];
    const float* dwb  = (const float*)d_in[4];
    const float* pw   = (const float*)d_in[5];
    const float* pb   = (const float*)d_in[6];
    const float* ab   = (const float*)d_in[7];
    float* out = (float*)d_out;

    int half = BB * CC * H2 * W2 / 2;  // 4,194,304
    wt_kernel<<<half / 256, 256>>>(x, wtf);

    size_t qsmem = 7504 * sizeof(float);    // 30016 B
    cudaFuncSetAttribute(qk_kernel, cudaFuncAttributeMaxDynamicSharedMemorySize, (int)qsmem);
    qk_kernel<<<NWIN * NHEADS, 256, qsmem>>>(dww, dwb, ab);

    size_t avsmem = 10752 * sizeof(float);  // 43008 B
    cudaFuncSetAttribute(av_kernel, cudaFuncAttributeMaxDynamicSharedMemorySize, (int)avsmem);
    av_kernel<<<NWIN, 256, avsmem>>>();

    size_t psmem = (32 * 258) * sizeof(float) + 2048 * sizeof(ull);  // 49408 B
    cudaFuncSetAttribute(proj_kernel, cudaFuncAttributeMaxDynamicSharedMemorySize, (int)psmem);
    proj_kernel<<<NWIN, 512, psmem>>>(pw, pb);

    iwt_kernel<<<half / 256, 256>>>(iwtf, out);
}

// round 16
// speedup vs baseline: 1.1621x; 1.1621x over previous
#include <cuda_runtime.h>
#include <cuda_bf16.h>
#include <math.h>

#define BB 2
#define CC 256
#define H2 128
#define W2 128
#define NWIN 512
#define NPOS 64
#define NHEADS 8
#define HD 32
#define ATT_SCALE 0.17677669529663687f
#define APAD 68     // probs row stride in smem (strided-n AV reads conflict-free)
#define LHP 72      // lh/q row stride: 72 ≡ 8 (mod 32) -> conv conflict-free
#define WPAD 260    // proj W row stride (floats): 1040B, 16B-aligned rows

typedef unsigned long long ull;
typedef unsigned int u32;

__device__ __forceinline__ ull pack2(float lo, float hi) {
    ull r; asm("mov.b64 %0, {%1,%2};" : "=l"(r) : "f"(lo), "f"(hi)); return r;
}
__device__ __forceinline__ void fma2(ull& d, ull a, ull b) {
    asm("fma.rn.f32x2 %0, %1, %2, %0;" : "+l"(d) : "l"(a), "l"(b));
}
__device__ __forceinline__ float2 unpack2(ull v) {
    float2 f; asm("mov.b64 {%0,%1}, %2;" : "=f"(f.x), "=f"(f.y) : "l"(v)); return f;
}
__device__ __forceinline__ void cpa16(u32 dst, const void* src) {
    asm volatile("cp.async.cg.shared.global [%0], [%1], 16;" :: "r"(dst), "l"(src));
}
#define CP_COMMIT() asm volatile("cp.async.commit_group;")
#define CP_WAIT(n)  asm volatile("cp.async.wait_group %0;" :: "n"(n))

// Scratch in window layout: [win][ch][p]
__device__ float g_llw  [NWIN * CC * NPOS];
__device__ float g_lhw  [NWIN * CC * NPOS];
__device__ float g_hlw  [NWIN * CC * NPOS];
__device__ float g_hhw  [NWIN * CC * NPOS];
__device__ float g_relu [NWIN * CC * NPOS];
__device__ float g_llout[NWIN * CC * NPOS];
// softmaxed attention probabilities: [win*8+h][n][m]
__device__ float g_attn [NWIN * NHEADS * NPOS * NPOS];
// transposed proj weight: [c][o]
__device__ float g_pwT  [CC * CC];

// ---------------------------------------------------------------------------
// Kernel A0: transpose proj weight (runs once, ~1us)
// ---------------------------------------------------------------------------
__global__ void tr_kernel(const float* __restrict__ pw) {
    int i = blockIdx.x * 256 + threadIdx.x;   // i = o*256 + c
    int o = i >> 8, c = i & 255;
    g_pwT[c * 256 + o] = pw[i];
}

// ---------------------------------------------------------------------------
// Kernel A: forward wavelet, 2 pixels per thread
// ---------------------------------------------------------------------------
__global__ void wt_kernel(const float* __restrict__ x, const float* __restrict__ wf) {
    int idx = blockIdx.x * blockDim.x + threadIdx.x;
    int xp = idx & 63;
    int y  = (idx >> 6) & 127;
    int ch = (idx >> 13) & 255;
    int b  = idx >> 21;
    int xx = xp << 1;

    const float* px = x + (((size_t)(b * CC + ch) * 256 + 2 * y) * 256 + 2 * xx);
    float4 r0 = *(const float4*)px;
    float4 r1 = *(const float4*)(px + 256);

    int win = b * 256 + (y >> 3) * 16 + (xx >> 3);
    int off = (win * CC + ch) * NPOS + (y & 7) * 8 + (xx & 7);
    const float* w = wf + ch * 16;

    float2 ll, lh, hl, hh;
    ll.x = w[0]*r0.x + w[1]*r0.y + w[2]*r1.x + w[3]*r1.y;
    ll.y = w[0]*r0.z + w[1]*r0.w + w[2]*r1.z + w[3]*r1.w;
    lh.x = w[4]*r0.x + w[5]*r0.y + w[6]*r1.x + w[7]*r1.y;
    lh.y = w[4]*r0.z + w[5]*r0.w + w[6]*r1.z + w[7]*r1.w;
    hl.x = w[8]*r0.x + w[9]*r0.y + w[10]*r1.x + w[11]*r1.y;
    hl.y = w[8]*r0.z + w[9]*r0.w + w[10]*r1.z + w[11]*r1.w;
    hh.x = w[12]*r0.x + w[13]*r0.y + w[14]*r1.x + w[15]*r1.y;
    hh.y = w[12]*r0.z + w[13]*r0.w + w[14]*r1.z + w[15]*r1.w;

    *(float2*)&g_llw[off] = ll;
    *(float2*)&g_lhw[off] = lh;
    *(float2*)&g_hlw[off] = hl;
    *(float2*)&g_hhw[off] = hh;
}

// ---------------------------------------------------------------------------
// Kernel B1: per-(window, head) conv + QK + softmax -> g_attn. Fully parallel.
// ---------------------------------------------------------------------------
__global__ void __launch_bounds__(256) qk_kernel(const float* __restrict__ dw_w,
                                                 const float* __restrict__ dw_b,
                                                 const float* __restrict__ ab) {
    extern __shared__ float sm[];
    float* s_w   = sm;          // 800
    float* s_lh  = sm + 800;    // 2296
    float* s_k   = sm + 3096;   // 2048
    float* s_q   = sm + 5144;   // 2296
    float* s_abr = sm + 7440;   // 64

    const int bid = blockIdx.x;
    const int win = bid >> 3, h = bid & 7;
    const int tid = threadIdx.x;
    const size_t hs = ((size_t)win * CC + h * HD) * NPOS;

    const u32 u_lh = (u32)__cvta_generic_to_shared(s_lh);
    const u32 u_w  = (u32)__cvta_generic_to_shared(s_w);
    const u32 u_k  = (u32)__cvta_generic_to_shared(s_k);

    {   // Group1: lh (padded rows) + conv weights
        const float4* src = (const float4*)(g_lhw + hs);
        #pragma unroll
        for (int kk = 0; kk < 2; ++kk) {
            int i = tid + kk * 256;
            int d = i >> 4, c = i & 15;
            cpa16(u_lh + (u32)(d * 18 + c) * 16, src + i);
        }
        if (tid < 200) cpa16(u_w + tid * 16, (const float4*)(dw_w + h * HD * 25) + tid);
        CP_COMMIT();
    }
    {   // Group2: k
        const float4* src = (const float4*)(g_hlw + hs);
        cpa16(u_k + tid * 16, src + tid);
        cpa16(u_k + (tid + 256) * 16, src + tid + 256);
        CP_COMMIT();
    }
    if (tid < 64) s_abr[tid] = ab[h * 64 + tid];

    const int cd  = tid >> 3;
    const int cix = tid & 7;
    const int tn  = (tid >> 4) << 2;
    const int tm  = (tid & 15) << 2;

    CP_WAIT(1);
    __syncthreads();

    // conv: q = dw5x5(lh) + bias
    {
        float wv[25];
        #pragma unroll
        for (int t = 0; t < 25; ++t) wv[t] = s_w[cd * 25 + t];
        float bias = __ldg(&dw_b[h * HD + cd]);
        #pragma unroll
        for (int iy = 0; iy < 8; ++iy) {
            float acc = bias;
            #pragma unroll
            for (int ky = 0; ky < 5; ++ky) {
                int yy = iy + ky - 2;
                if (yy < 0 || yy > 7) continue;
                #pragma unroll
                for (int kx = 0; kx < 5; ++kx) {
                    int xc = cix + kx - 2;
                    if (xc >= 0 && xc < 8)
                        acc += wv[ky * 5 + kx] * s_lh[cd * LHP + yy * 8 + xc];
                }
            }
            s_q[cd * LHP + iy * 8 + cix] = acc;
        }
    }
    CP_WAIT(0);
    __syncthreads();

    // QK + in-register softmax -> g_attn
    {
        ull a0[4] = {}, a1[4] = {};
        #pragma unroll 8
        for (int d = 0; d < HD; ++d) {
            ulonglong2 k2 = *(const ulonglong2*)&s_k[d * 64 + tm];
            float4 q4 = *(const float4*)&s_q[d * LHP + tn];
            ull qp[4] = {pack2(q4.x, q4.x), pack2(q4.y, q4.y),
                         pack2(q4.z, q4.z), pack2(q4.w, q4.w)};
            #pragma unroll
            for (int i = 0; i < 4; ++i) { fma2(a0[i], qp[i], k2.x); fma2(a1[i], qp[i], k2.y); }
        }
        float* pout = g_attn + (size_t)bid * (NPOS * NPOS);
        #pragma unroll
        for (int i = 0; i < 4; ++i) {
            int n = tn + i, yn = n >> 3, xn = n & 7;
            float2 pa = unpack2(a0[i]);
            float2 pb = unpack2(a1[i]);
            float raw[4] = {pa.x, pa.y, pb.x, pb.y};
            float vals[4];
            #pragma unroll
            for (int j = 0; j < 4; ++j) {
                int m = tm + j, ym = m >> 3, xm = m & 7;
                vals[j] = raw[j] * ATT_SCALE + s_abr[abs(yn - ym) * 8 + abs(xn - xm)];
            }
            float mx = fmaxf(fmaxf(vals[0], vals[1]), fmaxf(vals[2], vals[3]));
            mx = fmaxf(mx, __shfl_xor_sync(0xffffffff, mx, 1));
            mx = fmaxf(mx, __shfl_xor_sync(0xffffffff, mx, 2));
            mx = fmaxf(mx, __shfl_xor_sync(0xffffffff, mx, 4));
            mx = fmaxf(mx, __shfl_xor_sync(0xffffffff, mx, 8));
            float e0 = __expf(vals[0] - mx), e1 = __expf(vals[1] - mx);
            float e2 = __expf(vals[2] - mx), e3 = __expf(vals[3] - mx);
            float sum = e0 + e1 + e2 + e3;
            sum += __shfl_xor_sync(0xffffffff, sum, 1);
            sum += __shfl_xor_sync(0xffffffff, sum, 2);
            sum += __shfl_xor_sync(0xffffffff, sum, 4);
            sum += __shfl_xor_sync(0xffffffff, sum, 8);
            float inv = 1.0f / sum;
            *(float4*)&pout[n * 64 + tm] = make_float4(e0 * inv, e1 * inv, e2 * inv, e3 * inv);
        }
    }
}

// ---------------------------------------------------------------------------
// Kernel B2: serial AV cascade per window; probs double-buffered via cp.async
// ---------------------------------------------------------------------------
__global__ void __launch_bounds__(256) av_kernel() {
    extern __shared__ float sm[];
    float* s_v  = sm;          // 2048
    float* bufs = sm + 2048;   // 2 x 4352

    const int win = blockIdx.x;
    const int tid = threadIdx.x;
    const size_t wbase = (size_t)win * CC * NPOS;
    const u32 u_buf = (u32)__cvta_generic_to_shared(bufs);

    const int ad0 = (tid >> 4) << 1;   // 2 d's per thread
    const int ln  = tid & 15;          // n = ln + 16j

    {   // v(head0)
        const float4* sv = (const float4*)(g_llw + wbase);
        float4* dv = (float4*)s_v;
        dv[tid] = sv[tid]; dv[tid + 256] = sv[tid + 256];
    }
    // prefetch probs for heads 0 and 1
    #pragma unroll
    for (int g = 0; g < 2; ++g) {
        const float4* src = (const float4*)(g_attn + (size_t)(win * NHEADS + g) * (NPOS * NPOS));
        u32 dst = u_buf + (u32)(g * 4352 * 4);
        #pragma unroll
        for (int kk = 0; kk < 4; ++kk) {
            int c = tid + kk * 256;
            int row = c >> 4, col = c & 15;
            cpa16(dst + (u32)(row * APAD + col * 4) * 4, src + c);
        }
        CP_COMMIT();
    }

    float vnew[2][4];
    for (int h = 0; h < NHEADS; ++h) {
        if (h == NHEADS - 1) { CP_WAIT(0); } else { CP_WAIT(1); }
        __syncthreads();               // AV(h-1) done everywhere + probs(h) visible

        if (h > 0) {                   // deferred v-update
            #pragma unroll
            for (int i = 0; i < 2; ++i)
                #pragma unroll
                for (int j = 0; j < 4; ++j)
                    s_v[(ad0 + i) * 64 + ln + 16 * j] = vnew[i][j];
        }
        __syncwarp();

        const float* s_attn = bufs + (h & 1) * 4352;

        float pll[2][4];
        if (h < NHEADS - 1) {
            const float* src = g_llw + wbase + (size_t)(h + 1) * HD * NPOS;
            #pragma unroll
            for (int i = 0; i < 2; ++i)
                #pragma unroll
                for (int j = 0; j < 4; ++j)
                    pll[i][j] = __ldg(&src[(ad0 + i) * 64 + ln + 16 * j]);
        }

        ull acc2[2][4];
        #pragma unroll
        for (int i = 0; i < 2; ++i)
            #pragma unroll
            for (int j = 0; j < 4; ++j) acc2[i][j] = 0ULL;
        #pragma unroll 4
        for (int mq = 0; mq < 16; ++mq) {
            ulonglong2 vv0 = *(const ulonglong2*)&s_v[ad0 * 64 + mq * 4];
            ulonglong2 vv1 = *(const ulonglong2*)&s_v[(ad0 + 1) * 64 + mq * 4];
            ulonglong2 aa[4];
            #pragma unroll
            for (int j = 0; j < 4; ++j)
                aa[j] = *(const ulonglong2*)&s_attn[(ln + 16 * j) * APAD + mq * 4];
            #pragma unroll
            for (int j = 0; j < 4; ++j) {
                fma2(acc2[0][j], vv0.x, aa[j].x); fma2(acc2[0][j], vv0.y, aa[j].y);
                fma2(acc2[1][j], vv1.x, aa[j].x); fma2(acc2[1][j], vv1.y, aa[j].y);
            }
        }
        {
            size_t ob = wbase + (size_t)h * HD * NPOS;
            #pragma unroll
            for (int i = 0; i < 2; ++i) {
                int d = ad0 + i;
                #pragma unroll
                for (int j = 0; j < 4; ++j) {
                    float2 p = unpack2(acc2[i][j]);
                    float val = p.x + p.y;
                    g_relu[ob + d * 64 + ln + 16 * j] = fmaxf(val, 0.f);
                    if (h < NHEADS - 1) vnew[i][j] = val + pll[i][j];
                }
            }
        }
        __syncthreads();               // AV(h) fully done -> buf[h&1] reusable
        if (h + 2 < NHEADS) {          // prefetch probs(h+2) into buf[h&1]
            const float4* src = (const float4*)(g_attn + (size_t)(win * NHEADS + h + 2) * (NPOS * NPOS));
            u32 dst = u_buf + (u32)((h & 1) * 4352 * 4);
            #pragma unroll
            for (int kk = 0; kk < 4; ++kk) {
                int c = tid + kk * 256;
                int row = c >> 4, col = c & 15;
                cpa16(dst + (u32)(row * APAD + col * 4) * 4, src + c);
            }
            CP_COMMIT();
        }
    }
}

// ---------------------------------------------------------------------------
// Kernel B3: batched proj GEMM. R14 tile (4 o-pairs x 8 n), 256 threads.
// W double-buffered via cp.async from pre-transposed g_pwT; w-pairs via LDS.128.
// smem floats: 2 x (32*260) W bufs + 2048 ull Xd  = 82944 B
// ---------------------------------------------------------------------------
__global__ void __launch_bounds__(256) proj_kernel(const float* __restrict__ pb) {
    extern __shared__ float psm[];
    float* sW0 = psm;                         // buf0: [cl][o] stride 260
    float* sW1 = psm + 32 * WPAD;             // buf1
    ull*   sXd = (ull*)(psm + 2 * 32 * WPAD); // [cl][n] duplicated pairs

    const int win = blockIdx.x;
    const int tid = threadIdx.x;
    const int to  = (tid >> 3) << 3;          // 8 o's = 4 o-pairs (32B aligned)
    const int lnn = tid & 7;                  // n = lnn + 8j (broadcast reads)

    const u32 u_w0 = (u32)__cvta_generic_to_shared(sW0);
    const u32 u_w1 = (u32)__cvta_generic_to_shared(sW1);

    // preamble: async-stage W chunk 0 into buf0
    #pragma unroll
    for (int k = 0; k < 8; ++k) {
        int i = tid + k * 256;                // 16B-chunk index: row=cl, col16=o/4
        int row = i >> 6, col16 = i & 63;
        cpa16(u_w0 + (u32)(row * WPAD + col16 * 4) * 4,
              g_pwT + row * 256 + col16 * 4);
    }
    CP_COMMIT();

    ull acc2[4][8];
    #pragma unroll
    for (int i = 0; i < 4; ++i)
        #pragma unroll
        for (int j = 0; j < 8; ++j) acc2[i][j] = 0ULL;

    for (int c0 = 0; c0 < CC; c0 += 32) {
        // stage Xd(c0) (packed pairs; plain STS, latency overlapped with cp drain)
        {
            const float* xs = g_relu + (size_t)(win * CC + c0) * NPOS;
            #pragma unroll
            for (int k = 0; k < 8; ++k) {
                int j = tid + k * 256;
                float v = xs[j];
                sXd[j] = pack2(v, v);
            }
        }
        // async-stage next W chunk into the other buffer
        if (c0 < CC - 32) {
            u32 dst = ((c0 >> 5) & 1) ? u_w0 : u_w1;   // next buf = opposite parity
            const float* src = g_pwT + (c0 + 32) * 256;
            #pragma unroll
            for (int k = 0; k < 8; ++k) {
                int i = tid + k * 256;
                int row = i >> 6, col16 = i & 63;
                cpa16(dst + (u32)(row * WPAD + col16 * 4) * 4,
                      src + row * 256 + col16 * 4);
            }
            CP_COMMIT();
            CP_WAIT(1);                 // W(c0) ready
        } else {
            CP_WAIT(0);
        }
        __syncthreads();                // W(c0) + Xd(c0) visible to all

        const float* sW = ((c0 >> 5) & 1) ? sW1 : sW0;
        #pragma unroll 2
        for (int cl = 0; cl < 32; ++cl) {
            ulonglong2 wv0 = *(const ulonglong2*)&sW[cl * WPAD + to];      // (o0,o1),(o2,o3)
            ulonglong2 wv1 = *(const ulonglong2*)&sW[cl * WPAD + to + 4];  // (o4,o5),(o6,o7)
            ull w2[4] = {wv0.x, wv0.y, wv1.x, wv1.y};
            ull xd[8];
            #pragma unroll
            for (int j = 0; j < 8; ++j) xd[j] = sXd[cl * 64 + lnn + 8 * j];
            #pragma unroll
            for (int i = 0; i < 4; ++i)
                #pragma unroll
                for (int j = 0; j < 8; ++j) fma2(acc2[i][j], w2[i], xd[j]);
        }
        __syncthreads();                // before overwriting Xd next iteration
    }

    #pragma unroll
    for (int i = 0; i < 4; ++i) {
        int o0 = to + 2 * i;
        float b0 = pb[o0], b1 = pb[o0 + 1];
        float* out0 = g_llout + (size_t)(win * CC + o0) * NPOS;
        float* out1 = out0 + NPOS;
        #pragma unroll
        for (int j = 0; j < 8; ++j) {
            float2 p = unpack2(acc2[i][j]);
            int n = lnn + 8 * j;
            out0[n] = p.x + b0;
            out1[n] = p.y + b1;
        }
    }
}

// ---------------------------------------------------------------------------
// Kernel C: inverse wavelet, 2 cells per thread
// ---------------------------------------------------------------------------
__global__ void iwt_kernel(const float* __restrict__ iwf, float* __restrict__ out) {
    int idx = blockIdx.x * blockDim.x + threadIdx.x;
    int xp = idx & 63;
    int y  = (idx >> 6) & 127;
    int ch = (idx >> 13) & 255;
    int b  = idx >> 21;
    int xx = xp << 1;

    int win = b * 256 + (y >> 3) * 16 + (xx >> 3);
    int off = (win * CC + ch) * NPOS + (y & 7) * 8 + (xx & 7);
    float2 v0 = *(const float2*)&g_llout[off];
    float2 v1 = *(const float2*)&g_lhw[off];
    float2 v2 = *(const float2*)&g_hlw[off];
    float2 v3 = *(const float2*)&g_hhw[off];

    const float* w = iwf + ch * 16;
    float* po = out + (((size_t)(b * CC + ch) * 256 + 2 * y) * 256 + 2 * xx);

    float4 r0, r1;
    r0.x = w[0]*v0.x + w[4]*v1.x + w[8]*v2.x  + w[12]*v3.x;
    r0.y = w[1]*v0.x + w[5]*v1.x + w[9]*v2.x  + w[13]*v3.x;
    r0.z = w[0]*v0.y + w[4]*v1.y + w[8]*v2.y  + w[12]*v3.y;
    r0.w = w[1]*v0.y + w[5]*v1.y + w[9]*v2.y  + w[13]*v3.y;
    r1.x = w[2]*v0.x + w[6]*v1.x + w[10]*v2.x + w[14]*v3.x;
    r1.y = w[3]*v0.x + w[7]*v1.x + w[11]*v2.x + w[15]*v3.x;
    r1.z = w[2]*v0.y + w[6]*v1.y + w[10]*v2.y + w[14]*v3.y;
    r1.w = w[3]*v0.y + w[7]*v1.y + w[11]*v2.y + w[15]*v3.y;

    *(float4*)po         = r0;
    *(float4*)(po + 256) = r1;
}

// ---------------------------------------------------------------------------
extern "C" void kernel_launch(void* const* d_in, const int* in_sizes, int n_in,
                              void* d_out, int out_size) {
    const float* x    = (const float*)d_in[0];
    const float* wtf  = (const float*)d_in[1];
    const float* iwtf = (const float*)d_in[2];
    const float* dww  = (const float*)d_in[3];
    const float* dwb  = (const float*)d_in[4];
    const float* pw   = (const float*)d_in[5];
    const float* pb   = (const float*)d_in[6];
    const float* ab   = (const float*)d_in[7];
    float* out = (float*)d_out;

    tr_kernel<<<256, 256>>>(pw);

    int half = BB * CC * H2 * W2 / 2;  // 4,194,304
    wt_kernel<<<half / 256, 256>>>(x, wtf);

    size_t qsmem = 7504 * sizeof(float);    // 30016 B
    cudaFuncSetAttribute(qk_kernel, cudaFuncAttributeMaxDynamicSharedMemorySize, (int)qsmem);
    qk_kernel<<<NWIN * NHEADS, 256, qsmem>>>(dww, dwb, ab);

    size_t avsmem = 10752 * sizeof(float);  // 43008 B
    cudaFuncSetAttribute(av_kernel, cudaFuncAttributeMaxDynamicSharedMemorySize, (int)avsmem);
    av_kernel<<<NWIN, 256, avsmem>>>();

    size_t psmem = (2 * 32 * WPAD) * sizeof(float) + 2048 * sizeof(ull);  // 82944 B
    cudaFuncSetAttribute(proj_kernel, cudaFuncAttributeMaxDynamicSharedMemorySize, (int)psmem);
    proj_kernel<<<NWIN, 256, psmem>>>(pb);

    iwt_kernel<<<half / 256, 256>>>(iwtf, out);
}